// round 3
// baseline (speedup 1.0000x reference)
#include <cuda_runtime.h>
#include <math.h>

#define NODES   40000
#define EDGES   400000
#define GRAPHS  128
#define IN_F    768
#define HIDD    128
#define HEADS1  4
#define NEG_SLOPE 0.2f

// ---------------- scratch (device globals, no allocation) ----------------
__device__ float g_feat1[(size_t)NODES * HEADS1 * HIDD]; // x@W1           [N,512]
__device__ float g_h1  [(size_t)NODES * HEADS1 * HIDD];  // layer1 out     [N,512]
__device__ float g_feat2[(size_t)NODES * HIDD];          // h1@W2          [N,128]
__device__ float g_h2  [(size_t)NODES * HIDD];           // layer2 out     [N,128]
__device__ float g_tmp [(size_t)NODES * HIDD];           // node-MLP hidden
__device__ float g_el  [(size_t)NODES * HEADS1];
__device__ float g_er  [(size_t)NODES * HEADS1];
__device__ int   g_deg [NODES];
__device__ int   g_rowptr[NODES + 1];
__device__ int   g_next[NODES];
__device__ int   g_csrc[EDGES];      // src node of edges, grouped by dst

// ---------------- packed fp32x2 FMA (Blackwell FFMA2, 2x FFMA rate) ------
__device__ __forceinline__ void ffma2(float2& d, float2 a, float2 b) {
    unsigned long long& dd = reinterpret_cast<unsigned long long&>(d);
    unsigned long long aa = *reinterpret_cast<unsigned long long*>(&a);
    unsigned long long bb = *reinterpret_cast<unsigned long long*>(&b);
    asm("fma.rn.f32x2 %0, %1, %2, %0;" : "+l"(dd) : "l"(aa), "l"(bb));
}

// ---------------- CSR build ----------------
__global__ void zero_deg_k() {
    int i = blockIdx.x * blockDim.x + threadIdx.x;
    if (i < NODES) g_deg[i] = 0;
}
__global__ void count_k(const int* __restrict__ dst) {
    int e = blockIdx.x * blockDim.x + threadIdx.x;
    if (e < EDGES) atomicAdd(&g_deg[dst[e]], 1);
}
// single-block inclusive scan over g_deg -> g_rowptr, g_next (shfl-based)
__global__ void scan_k() {
    __shared__ int warpsum[32];
    __shared__ int carry;
    int lane = threadIdx.x & 31, wid = threadIdx.x >> 5;
    if (threadIdx.x == 0) { carry = 0; g_rowptr[0] = 0; }
    __syncthreads();
    for (int base = 0; base < NODES; base += 1024) {
        int i = base + threadIdx.x;
        int v = (i < NODES) ? g_deg[i] : 0;
        int x = v;
#pragma unroll
        for (int off = 1; off < 32; off <<= 1) {
            int y = __shfl_up_sync(0xffffffffu, x, off);
            if (lane >= off) x += y;
        }
        if (lane == 31) warpsum[wid] = x;
        __syncthreads();
        if (wid == 0) {
            int w = warpsum[lane];
#pragma unroll
            for (int off = 1; off < 32; off <<= 1) {
                int y = __shfl_up_sync(0xffffffffu, w, off);
                if (lane >= off) w += y;
            }
            warpsum[lane] = w;
        }
        __syncthreads();
        int add = carry + (wid > 0 ? warpsum[wid - 1] : 0);
        int incl = x + add;
        if (i < NODES) {
            g_rowptr[i + 1] = incl;
            g_next[i] = incl - v;   // == rowptr[i]
        }
        int total = warpsum[31];
        __syncthreads();
        if (threadIdx.x == 0) carry += total;
        __syncthreads();
    }
}
__global__ void fill_k(const int* __restrict__ src, const int* __restrict__ dst) {
    int e = blockIdx.x * blockDim.x + threadIdx.x;
    if (e < EDGES) {
        int d = dst[e];
        int p = atomicAdd(&g_next[d], 1);
        g_csrc[p] = src[e];
    }
}

// ---------------- SGEMM: C = act(A[MxK] @ B[KxN] + bias) ----------------
// 128x128x8 tile, 256 threads, 8x8 micro-tile via packed FFMA2.
// B stored duplicated in SMEM so both FFMA2 operands load pair-packed.
__global__ void __launch_bounds__(256, 2)
sgemm_k(const float* __restrict__ A, const float* __restrict__ B,
        const float* __restrict__ bias, float* __restrict__ C,
        int M, int N, int K, int relu) {
    __shared__ float As[8][128];
    __shared__ float Bs[8][256];   // each B value stored twice: {b,b}
    const int tid = threadIdx.x;
    const int bm = blockIdx.y * 128, bn = blockIdx.x * 128;
    const int tx = tid & 15, ty = tid >> 4;
    const int arow = tid >> 1, acol = (tid & 1) * 4;
    const int brow = tid >> 5, bcol = (tid & 31) * 4;

    float2 acc[4][8];   // [row-pair][col]
#pragma unroll
    for (int i = 0; i < 4; i++)
#pragma unroll
        for (int j = 0; j < 8; j++) acc[i][j] = make_float2(0.f, 0.f);

    const bool avalid = (bm + arow) < M;
    const float* Aptr = A + (size_t)(bm + arow) * K + acol;
    const float* Bptr = B + (size_t)brow * N + bn + bcol;

    // prologue load of tile k0=0
    float4 a4 = make_float4(0.f, 0.f, 0.f, 0.f);
    if (avalid) a4 = *(const float4*)(Aptr);
    float4 b4 = *(const float4*)(Bptr);

    for (int k0 = 0; k0 < K; k0 += 8) {
        // store current tile
        As[acol + 0][arow] = a4.x;
        As[acol + 1][arow] = a4.y;
        As[acol + 2][arow] = a4.z;
        As[acol + 3][arow] = a4.w;
        *(float4*)&Bs[brow][bcol * 2 + 0] = make_float4(b4.x, b4.x, b4.y, b4.y);
        *(float4*)&Bs[brow][bcol * 2 + 4] = make_float4(b4.z, b4.z, b4.w, b4.w);
        __syncthreads();

        // prefetch next tile into registers (hidden behind compute)
        if (k0 + 8 < K) {
            a4 = make_float4(0.f, 0.f, 0.f, 0.f);
            if (avalid) a4 = *(const float4*)(Aptr + k0 + 8);
            b4 = *(const float4*)(Bptr + (size_t)(k0 + 8) * N);
        }

#pragma unroll
        for (int kk = 0; kk < 8; kk++) {
            float4 a0 = *(float4*)&As[kk][ty * 4];
            float4 a1 = *(float4*)&As[kk][64 + ty * 4];
            float2 ap[4];
            ap[0] = make_float2(a0.x, a0.y);
            ap[1] = make_float2(a0.z, a0.w);
            ap[2] = make_float2(a1.x, a1.y);
            ap[3] = make_float2(a1.z, a1.w);
            float4 bq[4];
            bq[0] = *(float4*)&Bs[kk][tx * 8 + 0];
            bq[1] = *(float4*)&Bs[kk][tx * 8 + 4];
            bq[2] = *(float4*)&Bs[kk][128 + tx * 8 + 0];
            bq[3] = *(float4*)&Bs[kk][128 + tx * 8 + 4];
            const float2* bb = (const float2*)bq;  // 8 duplicated pairs {b,b}
#pragma unroll
            for (int j = 0; j < 8; j++)
#pragma unroll
                for (int ip = 0; ip < 4; ip++)
                    ffma2(acc[ip][j], ap[ip], bb[j]);
        }
        __syncthreads();
    }

    // epilogue: acc[ip][j].x -> row pair first row, .y -> second
#pragma unroll
    for (int ip = 0; ip < 4; ip++) {
        int rbase = (ip < 2) ? (ty * 4 + ip * 2) : (64 + ty * 4 + (ip - 2) * 2);
#pragma unroll
        for (int half = 0; half < 2; half++) {
            int gm = bm + rbase + half;
            if (gm >= M) continue;
#pragma unroll
            for (int jg = 0; jg < 2; jg++) {
                int col = bn + (jg ? (64 + tx * 4) : (tx * 4));
                float4 v;
                v.x = half ? acc[ip][jg * 4 + 0].y : acc[ip][jg * 4 + 0].x;
                v.y = half ? acc[ip][jg * 4 + 1].y : acc[ip][jg * 4 + 1].x;
                v.z = half ? acc[ip][jg * 4 + 2].y : acc[ip][jg * 4 + 2].x;
                v.w = half ? acc[ip][jg * 4 + 3].y : acc[ip][jg * 4 + 3].x;
                if (bias) {
                    v.x += bias[col + 0]; v.y += bias[col + 1];
                    v.z += bias[col + 2]; v.w += bias[col + 3];
                }
                if (relu) {
                    v.x = fmaxf(v.x, 0.f); v.y = fmaxf(v.y, 0.f);
                    v.z = fmaxf(v.z, 0.f); v.w = fmaxf(v.w, 0.f);
                }
                *(float4*)&C[(size_t)gm * N + col] = v;
            }
        }
    }
}

// ---------------- el/er: per-node per-head dot with attention vectors ---
__global__ void eler_k(const float* __restrict__ feat,
                       const float* __restrict__ al, const float* __restrict__ ar,
                       int heads) {
    int n = blockIdx.x;
    int h = threadIdx.x >> 5;
    int lane = threadIdx.x & 31;
    const float* f = feat + (size_t)n * heads * HIDD + h * HIDD;
    float sl = 0.f, sr = 0.f;
#pragma unroll
    for (int j = lane; j < HIDD; j += 32) {
        float v = f[j];
        sl += v * al[h * HIDD + j];
        sr += v * ar[h * HIDD + j];
    }
#pragma unroll
    for (int off = 16; off > 0; off >>= 1) {
        sl += __shfl_down_sync(0xffffffffu, sl, off);
        sr += __shfl_down_sync(0xffffffffu, sr, off);
    }
    if (lane == 0) {
        g_el[n * heads + h] = sl;
        g_er[n * heads + h] = sr;
    }
}

// ---------------- GAT aggregation: warp per (node, head) ----------------
__global__ void agg_k(const float* __restrict__ feat,
                      const float* __restrict__ bias,
                      float* __restrict__ out, int heads) {
    int n = blockIdx.x;
    int h = threadIdx.x >> 5;
    int lane = threadIdx.x & 31;
    int s0 = g_rowptr[n], s1 = g_rowptr[n + 1];
    float ern = g_er[n * heads + h];
    int stride = heads * HIDD;

    float m = -INFINITY;
    for (int i = s0; i < s1; i++) {
        int s = g_csrc[i];
        float e = g_el[s * heads + h] + ern;
        e = (e > 0.f) ? e : NEG_SLOPE * e;
        m = fmaxf(m, e);
    }
    float denom = 0.f;
    float a0 = 0.f, a1 = 0.f, a2 = 0.f, a3 = 0.f;
    for (int i = s0; i < s1; i++) {
        int s = g_csrc[i];
        float e = g_el[s * heads + h] + ern;
        e = (e > 0.f) ? e : NEG_SLOPE * e;
        float w = __expf(e - m);
        denom += w;
        const float* f = feat + (size_t)s * stride + h * HIDD + lane;
        a0 += w * f[0];
        a1 += w * f[32];
        a2 += w * f[64];
        a3 += w * f[96];
    }
    float inv = (s1 > s0) ? (1.f / denom) : 0.f;
    float* o = out + (size_t)n * stride + h * HIDD + lane;
    const float* b = bias + h * HIDD + lane;
    o[0]  = a0 * inv + b[0];
    o[32] = a1 * inv + b[32];
    o[64] = a2 * inv + b[64];
    o[96] = a3 * inv + b[96];
}

// ---------------- node head: out = tmp @ nW2 + nb2, warp per node -------
__global__ void head_k(const float* __restrict__ in, const float* __restrict__ W,
                       const float* __restrict__ b, float* __restrict__ out,
                       int nrows) {
    int warp = (blockIdx.x * blockDim.x + threadIdx.x) >> 5;
    int lane = threadIdx.x & 31;
    if (warp >= nrows) return;
    float p0 = 0.f, p1 = 0.f;
    const float* r = in + (size_t)warp * HIDD;
#pragma unroll
    for (int j = lane; j < HIDD; j += 32) {
        float v = r[j];
        p0 += v * W[j * 2 + 0];
        p1 += v * W[j * 2 + 1];
    }
#pragma unroll
    for (int off = 16; off > 0; off >>= 1) {
        p0 += __shfl_down_sync(0xffffffffu, p0, off);
        p1 += __shfl_down_sync(0xffffffffu, p1, off);
    }
    if (lane == 0) {
        out[warp * 2 + 0] = p0 + b[0];
        out[warp * 2 + 1] = p1 + b[1];
    }
}

// ------- fused graph pooling (sorted graph_ids -> binary search) + MLP ---
__global__ void gpool_mlp_k(const int* __restrict__ gid,
                            const float* __restrict__ gW1, const float* __restrict__ gb1,
                            const float* __restrict__ gW2, const float* __restrict__ gb2,
                            float* __restrict__ out) {
    int g = blockIdx.x;
    int t = threadIdx.x;   // 128 threads
    __shared__ int bounds[2];
    __shared__ float h[HIDD];
    __shared__ float hid[HIDD];
    __shared__ float red[HIDD];
    if (t < 2) {
        int target = g + t;
        int lo = 0, hi = NODES;
        while (lo < hi) {
            int mid = (lo + hi) >> 1;
            if (gid[mid] < target) lo = mid + 1; else hi = mid;
        }
        bounds[t] = lo;
    }
    __syncthreads();
    int s = bounds[0], e = bounds[1];
    float sum = 0.f;
    for (int n = s; n < e; n++) sum += g_h2[(size_t)n * HIDD + t];
    float inv = 1.f / fmaxf((float)(e - s), 1.f);
    h[t] = sum * inv;
    __syncthreads();
    float acc = gb1[t];
    for (int k = 0; k < HIDD; k++) acc += h[k] * gW1[k * HIDD + t];
    hid[t] = fmaxf(acc, 0.f);
    __syncthreads();
    for (int c = 0; c < 2; c++) {
        red[t] = hid[t] * gW2[t * 2 + c];
        __syncthreads();
        for (int off = 64; off > 0; off >>= 1) {
            if (t < off) red[t] += red[t + off];
            __syncthreads();
        }
        if (t == 0) out[g * 2 + c] = red[0] + gb2[c];
        __syncthreads();
    }
}

// ---------------- launch ----------------
extern "C" void kernel_launch(void* const* d_in, const int* in_sizes, int n_in,
                              void* d_out, int out_size) {
    const float* x   = (const float*)d_in[0];
    const int*  src  = (const int*)  d_in[1];
    const int*  dst  = (const int*)  d_in[2];
    const int*  gid  = (const int*)  d_in[3];
    const float* W1  = (const float*)d_in[4];
    const float* al1 = (const float*)d_in[5];
    const float* ar1 = (const float*)d_in[6];
    const float* b1  = (const float*)d_in[7];
    const float* W2  = (const float*)d_in[8];
    const float* al2 = (const float*)d_in[9];
    const float* ar2 = (const float*)d_in[10];
    const float* b2  = (const float*)d_in[11];
    const float* nW1 = (const float*)d_in[12];
    const float* nb1 = (const float*)d_in[13];
    const float* nW2 = (const float*)d_in[14];
    const float* nb2 = (const float*)d_in[15];
    const float* gW1 = (const float*)d_in[16];
    const float* gb1 = (const float*)d_in[17];
    const float* gW2 = (const float*)d_in[18];
    const float* gb2 = (const float*)d_in[19];
    float* out = (float*)d_out;

    float *p_feat1, *p_h1, *p_feat2, *p_h2, *p_tmp;
    cudaGetSymbolAddress((void**)&p_feat1, g_feat1);
    cudaGetSymbolAddress((void**)&p_h1,    g_h1);
    cudaGetSymbolAddress((void**)&p_feat2, g_feat2);
    cudaGetSymbolAddress((void**)&p_h2,    g_h2);
    cudaGetSymbolAddress((void**)&p_tmp,   g_tmp);

    // CSR build (shared by both GAT layers)
    zero_deg_k<<<(NODES + 255) / 256, 256>>>();
    count_k<<<(EDGES + 255) / 256, 256>>>(dst);
    scan_k<<<1, 1024>>>();
    fill_k<<<(EDGES + 255) / 256, 256>>>(src, dst);

    // ---- GAT layer 1 ----
    {
        dim3 grid(HEADS1 * HIDD / 128, (NODES + 127) / 128);
        sgemm_k<<<grid, 256>>>(x, W1, nullptr, p_feat1, NODES, HEADS1 * HIDD, IN_F, 0);
    }
    eler_k<<<NODES, HEADS1 * 32>>>(p_feat1, al1, ar1, HEADS1);
    agg_k<<<NODES, HEADS1 * 32>>>(p_feat1, b1, p_h1, HEADS1);

    // ---- GAT layer 2 ----
    {
        dim3 grid(HIDD / 128, (NODES + 127) / 128);
        sgemm_k<<<grid, 256>>>(p_h1, W2, nullptr, p_feat2, NODES, HIDD, HEADS1 * HIDD, 0);
    }
    eler_k<<<NODES, 32>>>(p_feat2, al2, ar2, 1);
    agg_k<<<NODES, 32>>>(p_feat2, b2, p_h2, 1);

    // ---- node MLP ----
    {
        dim3 grid(HIDD / 128, (NODES + 127) / 128);
        sgemm_k<<<grid, 256>>>(p_h2, nW1, nb1, p_tmp, NODES, HIDD, HIDD, 1);
    }
    head_k<<<(NODES * 32 + 255) / 256, 256>>>(p_tmp, nW2, nb2, out, NODES);

    // ---- fused graph pooling + MLP ----
    gpool_mlp_k<<<GRAPHS, HIDD>>>(gid, gW1, gb1, gW2, gb2, out + (size_t)NODES * 2);
}

// round 5
// speedup vs baseline: 2.7161x; 2.7161x over previous
#include <cuda_runtime.h>
#include <cuda_bf16.h>
#include <math.h>
#include <stdint.h>

#define NODES   40000
#define EDGES   400000
#define GRAPHS  128
#define IN_F    768
#define HIDD    128
#define HEADS1  4
#define NEG_SLOPE 0.2f

// ================= scratch (device globals, no allocation) =================
__device__ float g_feat1[(size_t)NODES * HEADS1 * HIDD];
__device__ float g_h1  [(size_t)NODES * HEADS1 * HIDD];
__device__ float g_feat2[(size_t)NODES * HIDD];
__device__ float g_h2  [(size_t)NODES * HIDD];
__device__ float g_tmp [(size_t)NODES * HIDD];
__device__ float g_el  [(size_t)NODES * HEADS1];
__device__ float g_er  [(size_t)NODES * HEADS1];
__device__ int   g_deg [NODES];
__device__ int   g_rowptr[NODES + 1];
__device__ int   g_next[NODES];
__device__ int   g_csrc[EDGES];
__device__ __align__(16) __nv_bfloat16 g_ahi[(size_t)NODES * IN_F];
__device__ __align__(16) __nv_bfloat16 g_alo[(size_t)NODES * IN_F];
__device__ __align__(16) __nv_bfloat16 g_bhi[IN_F * 512];
__device__ __align__(16) __nv_bfloat16 g_blo[IN_F * 512];

// ================= PTX helpers (sm_80-class, compile for .target sm_103) ===
__device__ __forceinline__ uint32_t smem_u32(const void* p) {
    uint32_t a;
    asm("{ .reg .u64 t; cvta.to.shared.u64 t, %1; cvt.u32.u64 %0, t; }" : "=r"(a) : "l"(p));
    return a;
}
__device__ __forceinline__ void cp16(uint32_t dst, const void* src, bool pred) {
    asm volatile("cp.async.cg.shared.global [%0], [%1], 16, %2;"
                 :: "r"(dst), "l"(src), "r"(pred ? 16 : 0) : "memory");
}
#define CP_COMMIT() asm volatile("cp.async.commit_group;" ::: "memory")
#define CP_WAIT(n)  asm volatile("cp.async.wait_group %0;" :: "n"(n) : "memory")

__device__ __forceinline__ void ldm_x4(uint32_t* r, uint32_t addr) {
    asm volatile("ldmatrix.sync.aligned.m8n8.x4.shared.b16 {%0,%1,%2,%3}, [%4];"
        : "=r"(r[0]), "=r"(r[1]), "=r"(r[2]), "=r"(r[3]) : "r"(addr));
}
__device__ __forceinline__ void ldm_x4t(uint32_t* r, uint32_t addr) {
    asm volatile("ldmatrix.sync.aligned.m8n8.x4.trans.shared.b16 {%0,%1,%2,%3}, [%4];"
        : "=r"(r[0]), "=r"(r[1]), "=r"(r[2]), "=r"(r[3]) : "r"(addr));
}
__device__ __forceinline__ void mma_bf16(float* d, const uint32_t* a, const uint32_t* b) {
    asm volatile("mma.sync.aligned.m16n8k16.row.col.f32.bf16.bf16.f32 "
        "{%0,%1,%2,%3}, {%4,%5,%6,%7}, {%8,%9}, {%0,%1,%2,%3};"
        : "+f"(d[0]), "+f"(d[1]), "+f"(d[2]), "+f"(d[3])
        : "r"(a[0]), "r"(a[1]), "r"(a[2]), "r"(a[3]), "r"(b[0]), "r"(b[1]));
}

// ================= split conversion kernels =================
__global__ void split_k(const float* __restrict__ in, __nv_bfloat16* __restrict__ hi,
                        __nv_bfloat16* __restrict__ lo, int n4) {
    int i = blockIdx.x * blockDim.x + threadIdx.x;
    if (i >= n4) return;
    float4 v = ((const float4*)in)[i];
    __nv_bfloat16 h0 = __float2bfloat16(v.x), h1 = __float2bfloat16(v.y);
    __nv_bfloat16 h2 = __float2bfloat16(v.z), h3 = __float2bfloat16(v.w);
    __nv_bfloat16 l0 = __float2bfloat16(v.x - __bfloat162float(h0));
    __nv_bfloat16 l1 = __float2bfloat16(v.y - __bfloat162float(h1));
    __nv_bfloat16 l2 = __float2bfloat16(v.z - __bfloat162float(h2));
    __nv_bfloat16 l3 = __float2bfloat16(v.w - __bfloat162float(h3));
    __nv_bfloat162* hp = (__nv_bfloat162*)hi;
    __nv_bfloat162* lp = (__nv_bfloat162*)lo;
    hp[i * 2 + 0] = __nv_bfloat162(h0, h1);
    hp[i * 2 + 1] = __nv_bfloat162(h2, h3);
    lp[i * 2 + 0] = __nv_bfloat162(l0, l1);
    lp[i * 2 + 1] = __nv_bfloat162(l2, l3);
}

// ================= tensor-core split-bf16 GEMM (mma.sync) =================
// C[M,Ntot] = A[M,K] @ B[K,Ntot], A/B pre-split bf16 hi/lo, B in natural [K,N].
// CTA 128x128, 8 warps (2x4), warp tile 64x32, k-chunk 32, double-buffered cp.async.
#define A_STRIDE_B 80    // 32 bf16 + 8 pad = 40 bf16 = 80 bytes
#define B_STRIDE_B 272   // 128 bf16 + 8 pad = 136 bf16 = 272 bytes
#define A_MAT_B   (128 * A_STRIDE_B)   // 10240
#define B_MAT_B   (32 * B_STRIDE_B)    // 8704
#define STAGE_B   (2 * A_MAT_B + 2 * B_MAT_B)  // 37888
#define SMEM_DYN  (2 * STAGE_B)                // 75776

__global__ void __launch_bounds__(256, 1)
tc_gemm(const __nv_bfloat16* __restrict__ Ahi, const __nv_bfloat16* __restrict__ Alo,
        const __nv_bfloat16* __restrict__ Bhi, const __nv_bfloat16* __restrict__ Blo,
        const float* __restrict__ bias, float* __restrict__ C,
        int M, int Ntot, int K, int relu) {
    extern __shared__ char smem[];
    const uint32_t s_base = smem_u32(smem);
    const int tid = threadIdx.x;
    const int lane = tid & 31, wid = tid >> 5;
    const int wm = wid & 1, wn = wid >> 1;   // warp grid 2x4
    const int bm = blockIdx.y * 128;
    const int bn = blockIdx.x * 128;
    const int niters = K >> 5;

    float acc[4][4][4];
#pragma unroll
    for (int i = 0; i < 4; i++)
#pragma unroll
        for (int j = 0; j < 4; j++) {
            acc[i][j][0] = 0.f; acc[i][j][1] = 0.f;
            acc[i][j][2] = 0.f; acc[i][j][3] = 0.f;
        }

    // ---- stage loader ----
    auto load_stage = [&](int it) {
        const int s = it & 1;
        const int k0 = it * 32;
        const uint32_t sb = s_base + s * STAGE_B;
        const __nv_bfloat16* Asrc[2] = { Ahi, Alo };
        const __nv_bfloat16* Bsrc[2] = { Bhi, Blo };
#pragma unroll
        for (int m = 0; m < 2; m++) {
#pragma unroll
            for (int i = 0; i < 2; i++) {
                int idx = tid + i * 256;          // 0..511
                int row = idx >> 2, cc = idx & 3; // 128 rows x 4 chunks
                bool p = (bm + row) < M;
                const void* src = Asrc[m] + (size_t)(bm + row) * K + k0 + cc * 8;
                cp16(sb + m * A_MAT_B + row * A_STRIDE_B + cc * 16, src, p);
            }
        }
#pragma unroll
        for (int m = 0; m < 2; m++) {
#pragma unroll
            for (int i = 0; i < 2; i++) {
                int idx = tid + i * 256;
                int row = idx >> 4, cc = idx & 15; // 32 rows x 16 chunks
                const void* src = Bsrc[m] + (size_t)(k0 + row) * Ntot + bn + cc * 8;
                cp16(sb + 2 * A_MAT_B + m * B_MAT_B + row * B_STRIDE_B + cc * 16, src, true);
            }
        }
        CP_COMMIT();
    };

    load_stage(0);

    for (int it = 0; it < niters; it++) {
        if (it + 1 < niters) load_stage(it + 1);
        if (it + 1 < niters) { CP_WAIT(1); } else { CP_WAIT(0); }
        __syncthreads();

        const uint32_t sb = s_base + (it & 1) * STAGE_B;
        const uint32_t a_hi_b = sb;
        const uint32_t a_lo_b = sb + A_MAT_B;
        const uint32_t b_hi_b = sb + 2 * A_MAT_B;
        const uint32_t b_lo_b = sb + 2 * A_MAT_B + B_MAT_B;

#pragma unroll
        for (int ks = 0; ks < 2; ks++) {
            uint32_t ah[4][4], al[4][4], bh[2][4], bl[2][4];
            // A frags: rows wm*64 + mi*16, k = ks*16
            const uint32_t a_off = (lane & 15) * A_STRIDE_B + ks * 32 + (lane >> 4) * 16;
#pragma unroll
            for (int mi = 0; mi < 4; mi++) {
                const uint32_t ro = (wm * 64 + mi * 16) * A_STRIDE_B;
                ldm_x4(ah[mi], a_hi_b + ro + a_off);
                ldm_x4(al[mi], a_lo_b + ro + a_off);
            }
            // B frags: k rows ks*16 + lane%16, cols wn*32 + np*16 + (lane/16)*8
            const uint32_t b_off = (ks * 16 + (lane & 15)) * B_STRIDE_B + (lane >> 4) * 16;
#pragma unroll
            for (int np = 0; np < 2; np++) {
                const uint32_t co = (wn * 32 + np * 16) * 2;
                ldm_x4t(bh[np], b_hi_b + b_off + co);
                ldm_x4t(bl[np], b_lo_b + b_off + co);
            }
#pragma unroll
            for (int mi = 0; mi < 4; mi++)
#pragma unroll
                for (int nf = 0; nf < 4; nf++) {
                    const uint32_t* bhp = &bh[nf >> 1][(nf & 1) * 2];
                    const uint32_t* blp = &bl[nf >> 1][(nf & 1) * 2];
                    mma_bf16(acc[mi][nf], ah[mi], bhp);
                    mma_bf16(acc[mi][nf], ah[mi], blp);
                    mma_bf16(acc[mi][nf], al[mi], bhp);
                }
        }
        __syncthreads();
    }

    // ---- epilogue ----
#pragma unroll
    for (int mi = 0; mi < 4; mi++) {
        int row0 = bm + wm * 64 + mi * 16 + (lane >> 2);
#pragma unroll
        for (int nf = 0; nf < 4; nf++) {
            int col = bn + wn * 32 + nf * 8 + (lane & 3) * 2;
            float b0 = bias ? bias[col] : 0.f;
            float b1 = bias ? bias[col + 1] : 0.f;
            float2 v0 = make_float2(acc[mi][nf][0] + b0, acc[mi][nf][1] + b1);
            float2 v1 = make_float2(acc[mi][nf][2] + b0, acc[mi][nf][3] + b1);
            if (relu) {
                v0.x = fmaxf(v0.x, 0.f); v0.y = fmaxf(v0.y, 0.f);
                v1.x = fmaxf(v1.x, 0.f); v1.y = fmaxf(v1.y, 0.f);
            }
            if (row0 < M)     *(float2*)&C[(size_t)row0 * Ntot + col] = v0;
            if (row0 + 8 < M) *(float2*)&C[(size_t)(row0 + 8) * Ntot + col] = v1;
        }
    }
}

// ================= CSR build =================
__global__ void zero_deg_k() {
    int i = blockIdx.x * blockDim.x + threadIdx.x;
    if (i < NODES) g_deg[i] = 0;
}
__global__ void count_k(const int* __restrict__ dst) {
    int e = blockIdx.x * blockDim.x + threadIdx.x;
    if (e < EDGES) atomicAdd(&g_deg[dst[e]], 1);
}
__global__ void scan_k() {
    __shared__ int warpsum[32];
    __shared__ int carry;
    int lane = threadIdx.x & 31, wid = threadIdx.x >> 5;
    if (threadIdx.x == 0) { carry = 0; g_rowptr[0] = 0; }
    __syncthreads();
    for (int base = 0; base < NODES; base += 1024) {
        int i = base + threadIdx.x;
        int v = (i < NODES) ? g_deg[i] : 0;
        int x = v;
#pragma unroll
        for (int off = 1; off < 32; off <<= 1) {
            int y = __shfl_up_sync(0xffffffffu, x, off);
            if (lane >= off) x += y;
        }
        if (lane == 31) warpsum[wid] = x;
        __syncthreads();
        if (wid == 0) {
            int w = warpsum[lane];
#pragma unroll
            for (int off = 1; off < 32; off <<= 1) {
                int y = __shfl_up_sync(0xffffffffu, w, off);
                if (lane >= off) w += y;
            }
            warpsum[lane] = w;
        }
        __syncthreads();
        int add = carry + (wid > 0 ? warpsum[wid - 1] : 0);
        int incl = x + add;
        if (i < NODES) {
            g_rowptr[i + 1] = incl;
            g_next[i] = incl - v;
        }
        int total = warpsum[31];
        __syncthreads();
        if (threadIdx.x == 0) carry += total;
        __syncthreads();
    }
}
__global__ void fill_k(const int* __restrict__ src, const int* __restrict__ dst) {
    int e = blockIdx.x * blockDim.x + threadIdx.x;
    if (e < EDGES) {
        int d = dst[e];
        int p = atomicAdd(&g_next[d], 1);
        g_csrc[p] = src[e];
    }
}

// ================= GAT attention pieces =================
__global__ void eler_k(const float* __restrict__ feat,
                       const float* __restrict__ al, const float* __restrict__ ar,
                       int heads) {
    int n = blockIdx.x;
    int h = threadIdx.x >> 5;
    int lane = threadIdx.x & 31;
    const float* f = feat + (size_t)n * heads * HIDD + h * HIDD;
    float sl = 0.f, sr = 0.f;
#pragma unroll
    for (int j = lane; j < HIDD; j += 32) {
        float v = f[j];
        sl += v * al[h * HIDD + j];
        sr += v * ar[h * HIDD + j];
    }
#pragma unroll
    for (int off = 16; off > 0; off >>= 1) {
        sl += __shfl_down_sync(0xffffffffu, sl, off);
        sr += __shfl_down_sync(0xffffffffu, sr, off);
    }
    if (lane == 0) {
        g_el[n * heads + h] = sl;
        g_er[n * heads + h] = sr;
    }
}

__global__ void agg_k(const float* __restrict__ feat,
                      const float* __restrict__ bias,
                      float* __restrict__ out, int heads) {
    int n = blockIdx.x;
    int h = threadIdx.x >> 5;
    int lane = threadIdx.x & 31;
    int s0 = g_rowptr[n], s1 = g_rowptr[n + 1];
    float ern = g_er[n * heads + h];
    int stride = heads * HIDD;

    float m = -INFINITY;
    for (int i = s0; i < s1; i++) {
        int s = g_csrc[i];
        float e = g_el[s * heads + h] + ern;
        e = (e > 0.f) ? e : NEG_SLOPE * e;
        m = fmaxf(m, e);
    }
    float denom = 0.f;
    float a0 = 0.f, a1 = 0.f, a2 = 0.f, a3 = 0.f;
    for (int i = s0; i < s1; i++) {
        int s = g_csrc[i];
        float e = g_el[s * heads + h] + ern;
        e = (e > 0.f) ? e : NEG_SLOPE * e;
        float w = __expf(e - m);
        denom += w;
        const float* f = feat + (size_t)s * stride + h * HIDD + lane;
        a0 += w * f[0];
        a1 += w * f[32];
        a2 += w * f[64];
        a3 += w * f[96];
    }
    float inv = (s1 > s0) ? (1.f / denom) : 0.f;
    float* o = out + (size_t)n * stride + h * HIDD + lane;
    const float* b = bias + h * HIDD + lane;
    o[0]  = a0 * inv + b[0];
    o[32] = a1 * inv + b[32];
    o[64] = a2 * inv + b[64];
    o[96] = a3 * inv + b[96];
}

// ================= node output head =================
__global__ void head_k(const float* __restrict__ in, const float* __restrict__ W,
                       const float* __restrict__ b, float* __restrict__ out,
                       int nrows) {
    int warp = (blockIdx.x * blockDim.x + threadIdx.x) >> 5;
    int lane = threadIdx.x & 31;
    if (warp >= nrows) return;
    float p0 = 0.f, p1 = 0.f;
    const float* r = in + (size_t)warp * HIDD;
#pragma unroll
    for (int j = lane; j < HIDD; j += 32) {
        float v = r[j];
        p0 += v * W[j * 2 + 0];
        p1 += v * W[j * 2 + 1];
    }
#pragma unroll
    for (int off = 16; off > 0; off >>= 1) {
        p0 += __shfl_down_sync(0xffffffffu, p0, off);
        p1 += __shfl_down_sync(0xffffffffu, p1, off);
    }
    if (lane == 0) {
        out[warp * 2 + 0] = p0 + b[0];
        out[warp * 2 + 1] = p1 + b[1];
    }
}

// ===== fused graph pooling (sorted graph_ids -> binary search) + MLP =====
__global__ void gpool_mlp_k(const int* __restrict__ gid,
                            const float* __restrict__ gW1, const float* __restrict__ gb1,
                            const float* __restrict__ gW2, const float* __restrict__ gb2,
                            float* __restrict__ out) {
    int g = blockIdx.x;
    int t = threadIdx.x;
    __shared__ int bounds[2];
    __shared__ float h[HIDD];
    __shared__ float hid[HIDD];
    __shared__ float red[HIDD];
    if (t < 2) {
        int target = g + t;
        int lo = 0, hi = NODES;
        while (lo < hi) {
            int mid = (lo + hi) >> 1;
            if (gid[mid] < target) lo = mid + 1; else hi = mid;
        }
        bounds[t] = lo;
    }
    __syncthreads();
    int s = bounds[0], e = bounds[1];
    float sum = 0.f;
    for (int n = s; n < e; n++) sum += g_h2[(size_t)n * HIDD + t];
    float inv = 1.f / fmaxf((float)(e - s), 1.f);
    h[t] = sum * inv;
    __syncthreads();
    float acc = gb1[t];
    for (int k = 0; k < HIDD; k++) acc += h[k] * gW1[k * HIDD + t];
    hid[t] = fmaxf(acc, 0.f);
    __syncthreads();
    for (int c = 0; c < 2; c++) {
        red[t] = hid[t] * gW2[t * 2 + c];
        __syncthreads();
        for (int off = 64; off > 0; off >>= 1) {
            if (t < off) red[t] += red[t + off];
            __syncthreads();
        }
        if (t == 0) out[g * 2 + c] = red[0] + gb2[c];
        __syncthreads();
    }
}

// ================= launch =================
extern "C" void kernel_launch(void* const* d_in, const int* in_sizes, int n_in,
                              void* d_out, int out_size) {
    const float* x   = (const float*)d_in[0];
    const int*  src  = (const int*)  d_in[1];
    const int*  dst  = (const int*)  d_in[2];
    const int*  gid  = (const int*)  d_in[3];
    const float* W1  = (const float*)d_in[4];
    const float* al1 = (const float*)d_in[5];
    const float* ar1 = (const float*)d_in[6];
    const float* b1  = (const float*)d_in[7];
    const float* W2  = (const float*)d_in[8];
    const float* al2 = (const float*)d_in[9];
    const float* ar2 = (const float*)d_in[10];
    const float* b2  = (const float*)d_in[11];
    const float* nW1 = (const float*)d_in[12];
    const float* nb1 = (const float*)d_in[13];
    const float* nW2 = (const float*)d_in[14];
    const float* nb2 = (const float*)d_in[15];
    const float* gW1 = (const float*)d_in[16];
    const float* gb1 = (const float*)d_in[17];
    const float* gW2 = (const float*)d_in[18];
    const float* gb2 = (const float*)d_in[19];
    float* out = (float*)d_out;

    float *p_feat1, *p_h1, *p_feat2, *p_h2, *p_tmp;
    __nv_bfloat16 *p_ahi, *p_alo, *p_bhi, *p_blo;
    cudaGetSymbolAddress((void**)&p_feat1, g_feat1);
    cudaGetSymbolAddress((void**)&p_h1,    g_h1);
    cudaGetSymbolAddress((void**)&p_feat2, g_feat2);
    cudaGetSymbolAddress((void**)&p_h2,    g_h2);
    cudaGetSymbolAddress((void**)&p_tmp,   g_tmp);
    cudaGetSymbolAddress((void**)&p_ahi,   g_ahi);
    cudaGetSymbolAddress((void**)&p_alo,   g_alo);
    cudaGetSymbolAddress((void**)&p_bhi,   g_bhi);
    cudaGetSymbolAddress((void**)&p_blo,   g_blo);

    cudaFuncSetAttribute(tc_gemm, cudaFuncAttributeMaxDynamicSharedMemorySize, SMEM_DYN);

    const int MT = (NODES + 127) / 128;  // 313 row tiles

    // CSR build
    zero_deg_k<<<(NODES + 255) / 256, 256>>>();
    count_k<<<(EDGES + 255) / 256, 256>>>(dst);
    scan_k<<<1, 1024>>>();
    fill_k<<<(EDGES + 255) / 256, 256>>>(src, dst);

    // ---- GAT layer 1: feat1 = x @ W1 ----
    split_k<<<(NODES * IN_F / 4 + 255) / 256, 256>>>(x, p_ahi, p_alo, NODES * IN_F / 4);
    split_k<<<(IN_F * 512 / 4 + 255) / 256, 256>>>(W1, p_bhi, p_blo, IN_F * 512 / 4);
    tc_gemm<<<dim3(4, MT), 256, SMEM_DYN>>>(p_ahi, p_alo, p_bhi, p_blo, nullptr,
                                            p_feat1, NODES, 512, IN_F, 0);
    eler_k<<<NODES, HEADS1 * 32>>>(p_feat1, al1, ar1, HEADS1);
    agg_k<<<NODES, HEADS1 * 32>>>(p_feat1, b1, p_h1, HEADS1);

    // ---- GAT layer 2: feat2 = h1 @ W2 ----
    split_k<<<(NODES * 512 / 4 + 255) / 256, 256>>>(p_h1, p_ahi, p_alo, NODES * 512 / 4);
    split_k<<<(512 * HIDD / 4 + 255) / 256, 256>>>(W2, p_bhi, p_blo, 512 * HIDD / 4);
    tc_gemm<<<dim3(1, MT), 256, SMEM_DYN>>>(p_ahi, p_alo, p_bhi, p_blo, nullptr,
                                            p_feat2, NODES, HIDD, 512, 0);
    eler_k<<<NODES, 32>>>(p_feat2, al2, ar2, 1);
    agg_k<<<NODES, 32>>>(p_feat2, b2, p_h2, 1);

    // ---- node MLP: tmp = relu(h2 @ nW1 + nb1) ----
    split_k<<<(NODES * HIDD / 4 + 255) / 256, 256>>>(p_h2, p_ahi, p_alo, NODES * HIDD / 4);
    split_k<<<(HIDD * HIDD / 4 + 255) / 256, 256>>>(nW1, p_bhi, p_blo, HIDD * HIDD / 4);
    tc_gemm<<<dim3(1, MT), 256, SMEM_DYN>>>(p_ahi, p_alo, p_bhi, p_blo, nb1,
                                            p_tmp, NODES, HIDD, HIDD, 1);
    head_k<<<(NODES * 32 + 255) / 256, 256>>>(p_tmp, nW2, nb2, out, NODES);

    // ---- fused graph pooling + MLP ----
    gpool_mlp_k<<<GRAPHS, HIDD>>>(gid, gW1, gb1, gW2, gb2, out + (size_t)NODES * 2);
}